// round 3
// baseline (speedup 1.0000x reference)
#include <cuda_runtime.h>
#include <math.h>

#define N_NODESK 50000
#define N_EDGESK 800000
#define F_INK    128
#define C1K      256     // HEADS*HID
#define HEADSK   8
#define NBLK_SCAN 196    // ceil(50000/256)

// ---------------- scratch (device globals: allocation-free contract) ----------------
__device__ float g_h1[N_NODESK * C1K];     // x @ W1 (51.2 MB)
__device__ float g_as1[N_NODESK * HEADSK];
__device__ float g_ad1[N_NODESK * HEADSK];
__device__ float g_h2[N_NODESK * 2];
__device__ float g_as2[N_NODESK];
__device__ float g_ad2[N_NODESK];
__device__ int   g_cnt[N_NODESK];
__device__ int   g_rowptr[N_NODESK + 1];
__device__ int   g_cursor[N_NODESK];
__device__ int   g_col[N_EDGESK];          // src ids grouped by dst
__device__ int   g_bsum[NBLK_SCAN];
__device__ int   g_boff[NBLK_SCAN];

// ---------------- CSR build ----------------
__global__ void zero_cnt_kernel() {
    int i = blockIdx.x * blockDim.x + threadIdx.x;
    if (i < N_NODESK) g_cnt[i] = 0;
}

__global__ void hist_kernel(const int* __restrict__ dst) {
    int e = blockIdx.x * blockDim.x + threadIdx.x;
    if (e < N_EDGESK) atomicAdd(&g_cnt[dst[e]], 1);
}

// hierarchical scan: per-block sums
__global__ void blocksum_kernel() {
    int i = blockIdx.x * 256 + threadIdx.x;
    int v = (i < N_NODESK) ? g_cnt[i] : 0;
    __shared__ int ws[8];
    int lane = threadIdx.x & 31, w = threadIdx.x >> 5;
#pragma unroll
    for (int o = 16; o; o >>= 1) v += __shfl_xor_sync(0xffffffffu, v, o);
    if (lane == 0) ws[w] = v;
    __syncthreads();
    if (threadIdx.x == 0) {
        int s = 0;
#pragma unroll
        for (int k = 0; k < 8; k++) s += ws[k];
        g_bsum[blockIdx.x] = s;
    }
}

// scan the 196 block sums (exclusive)
__global__ void scantop_kernel() {
    __shared__ int sh[256];
    int v = (threadIdx.x < NBLK_SCAN) ? g_bsum[threadIdx.x] : 0;
    sh[threadIdx.x] = v;
    __syncthreads();
    for (int off = 1; off < 256; off <<= 1) {
        int t = (threadIdx.x >= off) ? sh[threadIdx.x - off] : 0;
        __syncthreads();
        sh[threadIdx.x] += t;
        __syncthreads();
    }
    if (threadIdx.x < NBLK_SCAN) g_boff[threadIdx.x] = sh[threadIdx.x] - v;
}

// local scan + add block offset -> rowptr / cursor
__global__ void scanlocal_kernel() {
    __shared__ int sh[256];
    int i = blockIdx.x * 256 + threadIdx.x;
    int v = (i < N_NODESK) ? g_cnt[i] : 0;
    sh[threadIdx.x] = v;
    __syncthreads();
    for (int off = 1; off < 256; off <<= 1) {
        int t = (threadIdx.x >= off) ? sh[threadIdx.x - off] : 0;
        __syncthreads();
        sh[threadIdx.x] += t;
        __syncthreads();
    }
    int incl = sh[threadIdx.x];
    int base = g_boff[blockIdx.x];
    if (i < N_NODESK) {
        int excl = base + incl - v;
        g_rowptr[i] = excl;
        g_cursor[i] = excl;
        if (i == N_NODESK - 1) g_rowptr[N_NODESK] = base + incl;
    }
}

__global__ void scatter_kernel(const int* __restrict__ src, const int* __restrict__ dst) {
    int e = blockIdx.x * blockDim.x + threadIdx.x;
    if (e < N_EDGESK) {
        int pos = atomicAdd(&g_cursor[dst[e]], 1);
        g_col[pos] = src[e];
    }
}

// ---------------- SGEMM: g_h1 = x[M,128] @ W1[128,256] ----------------
// 128x128 tile, 8x8 per-thread micro-tile, double-buffered smem.
__global__ __launch_bounds__(256) void sgemm_kernel(const float* __restrict__ A,
                                                    const float* __restrict__ B) {
    __shared__ float As[2][16][128];
    __shared__ float Bs[2][16][128];
    const int tid = threadIdx.x;
    const int bm = blockIdx.y * 128;
    const int bn = blockIdx.x * 128;
    const int tx = tid & 15, ty = tid >> 4;

    const int arow = tid >> 2;        // 0..63 (slot2 adds 64)
    const int akc  = tid & 3;         // k-chunk of 4
    const int bkr  = tid >> 5;        // 0..7 (slot2 adds 8)
    const int bcc  = tid & 31;        // col chunk of 4

    float acc[8][8];
#pragma unroll
    for (int i = 0; i < 8; i++)
#pragma unroll
        for (int j = 0; j < 8; j++) acc[i][j] = 0.f;

    float4 aR0, aR1, bR0, bR1;
    const float4 z4 = make_float4(0.f, 0.f, 0.f, 0.f);

    // prefetch tile 0
    {
        int r0 = bm + arow, r1 = bm + arow + 64;
        aR0 = (r0 < N_NODESK) ? *(const float4*)(A + (size_t)r0 * F_INK + akc * 4) : z4;
        aR1 = (r1 < N_NODESK) ? *(const float4*)(A + (size_t)r1 * F_INK + akc * 4) : z4;
        bR0 = *(const float4*)(B + (size_t)bkr * C1K + bn + bcc * 4);
        bR1 = *(const float4*)(B + (size_t)(bkr + 8) * C1K + bn + bcc * 4);
    }
    As[0][akc * 4 + 0][arow] = aR0.x; As[0][akc * 4 + 1][arow] = aR0.y;
    As[0][akc * 4 + 2][arow] = aR0.z; As[0][akc * 4 + 3][arow] = aR0.w;
    As[0][akc * 4 + 0][arow + 64] = aR1.x; As[0][akc * 4 + 1][arow + 64] = aR1.y;
    As[0][akc * 4 + 2][arow + 64] = aR1.z; As[0][akc * 4 + 3][arow + 64] = aR1.w;
    *(float4*)&Bs[0][bkr][bcc * 4] = bR0;
    *(float4*)&Bs[0][bkr + 8][bcc * 4] = bR1;
    __syncthreads();

    int buf = 0;
#pragma unroll
    for (int t = 0; t < 8; ++t) {
        if (t < 7) {
            int kt = (t + 1) * 16;
            int r0 = bm + arow, r1 = bm + arow + 64;
            aR0 = (r0 < N_NODESK) ? *(const float4*)(A + (size_t)r0 * F_INK + kt + akc * 4) : z4;
            aR1 = (r1 < N_NODESK) ? *(const float4*)(A + (size_t)r1 * F_INK + kt + akc * 4) : z4;
            bR0 = *(const float4*)(B + (size_t)(kt + bkr) * C1K + bn + bcc * 4);
            bR1 = *(const float4*)(B + (size_t)(kt + bkr + 8) * C1K + bn + bcc * 4);
        }
#pragma unroll
        for (int k = 0; k < 16; ++k) {
            float4 a0 = *(const float4*)&As[buf][k][ty * 8];
            float4 a1 = *(const float4*)&As[buf][k][ty * 8 + 4];
            float4 b0 = *(const float4*)&Bs[buf][k][tx * 8];
            float4 b1 = *(const float4*)&Bs[buf][k][tx * 8 + 4];
            float av[8] = {a0.x, a0.y, a0.z, a0.w, a1.x, a1.y, a1.z, a1.w};
            float bv[8] = {b0.x, b0.y, b0.z, b0.w, b1.x, b1.y, b1.z, b1.w};
#pragma unroll
            for (int i = 0; i < 8; i++)
#pragma unroll
                for (int j = 0; j < 8; j++) acc[i][j] += av[i] * bv[j];
        }
        if (t < 7) {
            int nb = buf ^ 1;
            As[nb][akc * 4 + 0][arow] = aR0.x; As[nb][akc * 4 + 1][arow] = aR0.y;
            As[nb][akc * 4 + 2][arow] = aR0.z; As[nb][akc * 4 + 3][arow] = aR0.w;
            As[nb][akc * 4 + 0][arow + 64] = aR1.x; As[nb][akc * 4 + 1][arow + 64] = aR1.y;
            As[nb][akc * 4 + 2][arow + 64] = aR1.z; As[nb][akc * 4 + 3][arow + 64] = aR1.w;
            *(float4*)&Bs[nb][bkr][bcc * 4] = bR0;
            *(float4*)&Bs[nb][bkr + 8][bcc * 4] = bR1;
            __syncthreads();
            buf = nb;
        }
    }
#pragma unroll
    for (int i = 0; i < 8; i++) {
        int r = bm + ty * 8 + i;
        if (r < N_NODESK) {
            float4 o0 = make_float4(acc[i][0], acc[i][1], acc[i][2], acc[i][3]);
            float4 o1 = make_float4(acc[i][4], acc[i][5], acc[i][6], acc[i][7]);
            *(float4*)(g_h1 + (size_t)r * C1K + bn + tx * 8) = o0;
            *(float4*)(g_h1 + (size_t)r * C1K + bn + tx * 8 + 4) = o1;
        }
    }
}

// ---------------- alpha1: per (node, head) dot of h1 slice with a1 vectors ----------------
__global__ void alpha1_kernel(const float* __restrict__ a_src, const float* __restrict__ a_dst) {
    int t = blockIdx.x * blockDim.x + threadIdx.x;
    if (t >= N_NODESK * HEADSK) return;
    int n = t >> 3, h = t & 7;
    const float4* hr = (const float4*)(g_h1 + (size_t)n * C1K + h * 32);
    const float4* av = (const float4*)(a_src + h * 32);
    const float4* bv = (const float4*)(a_dst + h * 32);
    float s = 0.f, d = 0.f;
#pragma unroll
    for (int i = 0; i < 8; i++) {
        float4 v = hr[i];
        float4 a = av[i];
        float4 b = bv[i];
        s += v.x * a.x + v.y * a.y + v.z * a.z + v.w * a.w;
        d += v.x * b.x + v.y * b.y + v.z * b.z + v.w * b.w;
    }
    g_as1[t] = s;
    g_ad1[t] = d;
}

__device__ __forceinline__ float lrelu02(float x) { return x > 0.f ? x : 0.2f * x; }
__device__ __forceinline__ float eluf(float x)    { return x > 0.f ? x : expm1f(x); }

// ---------------- layer-1 aggregation fused with layer-2 node transform ----------------
// warp per dst node. lane l owns channels [4l,4l+3] (head l/8) and [128+4l,128+4l+3].
// hout = elu( (Σ_e w_e h1[src_e]) / Σ_e w_e + b1 ) is kept in registers and immediately
// contracted with W2 -> g_h2 / g_as2 / g_ad2 (hout never materialized).
__global__ __launch_bounds__(256) void agg1_kernel(const float* __restrict__ b1,
                                                   const float* __restrict__ W2,
                                                   const float* __restrict__ a2s,
                                                   const float* __restrict__ a2d) {
    int warp = (blockIdx.x * blockDim.x + threadIdx.x) >> 5;
    int lane = threadIdx.x & 31;
    if (warp >= N_NODESK) return;
    int n = warp;
    int hA = lane >> 3, hB = 4 + (lane >> 3);
    float adA = g_ad1[n * 8 + hA];
    float adB = g_ad1[n * 8 + hB];
    float4 accA = make_float4(0.f, 0.f, 0.f, 0.f);
    float4 accB = make_float4(0.f, 0.f, 0.f, 0.f);
    float denA = 0.f, denB = 0.f;
    int beg = g_rowptr[n], end = g_rowptr[n + 1];
    for (int e = beg - 1; e < end; ++e) {       // e == beg-1 is the self loop
        int s = (e < beg) ? n : g_col[e];
        float wA = expf(lrelu02(g_as1[s * 8 + hA] + adA));
        float wB = expf(lrelu02(g_as1[s * 8 + hB] + adB));
        const float4* row = (const float4*)(g_h1 + (size_t)s * C1K);
        float4 vA = row[lane];
        float4 vB = row[32 + lane];
        accA.x += wA * vA.x; accA.y += wA * vA.y; accA.z += wA * vA.z; accA.w += wA * vA.w;
        accB.x += wB * vB.x; accB.y += wB * vB.y; accB.z += wB * vB.z; accB.w += wB * vB.w;
        denA += wA; denB += wB;
    }
    float rA = 1.f / denA, rB = 1.f / denB;
    const float4 bA = *(const float4*)(b1 + 4 * lane);
    const float4 bB = *(const float4*)(b1 + 128 + 4 * lane);
    float4 oA, oB;
    oA.x = eluf(accA.x * rA + bA.x); oA.y = eluf(accA.y * rA + bA.y);
    oA.z = eluf(accA.z * rA + bA.z); oA.w = eluf(accA.w * rA + bA.w);
    oB.x = eluf(accB.x * rB + bB.x); oB.y = eluf(accB.y * rB + bB.y);
    oB.z = eluf(accB.z * rB + bB.z); oB.w = eluf(accB.w * rB + bB.w);

    // layer-2 node transform: h2 = hout @ W2 (W2: [256,2] row-major)
    int cA = 4 * lane, cB = 128 + 4 * lane;
    float acc0 = oA.x * W2[(cA + 0) * 2] + oA.y * W2[(cA + 1) * 2]
               + oA.z * W2[(cA + 2) * 2] + oA.w * W2[(cA + 3) * 2]
               + oB.x * W2[(cB + 0) * 2] + oB.y * W2[(cB + 1) * 2]
               + oB.z * W2[(cB + 2) * 2] + oB.w * W2[(cB + 3) * 2];
    float acc1 = oA.x * W2[(cA + 0) * 2 + 1] + oA.y * W2[(cA + 1) * 2 + 1]
               + oA.z * W2[(cA + 2) * 2 + 1] + oA.w * W2[(cA + 3) * 2 + 1]
               + oB.x * W2[(cB + 0) * 2 + 1] + oB.y * W2[(cB + 1) * 2 + 1]
               + oB.z * W2[(cB + 2) * 2 + 1] + oB.w * W2[(cB + 3) * 2 + 1];
#pragma unroll
    for (int o = 16; o; o >>= 1) {
        acc0 += __shfl_xor_sync(0xffffffffu, acc0, o);
        acc1 += __shfl_xor_sync(0xffffffffu, acc1, o);
    }
    if (lane == 0) {
        g_h2[n * 2 + 0] = acc0;
        g_h2[n * 2 + 1] = acc1;
        g_as2[n] = acc0 * a2s[0] + acc1 * a2s[1];
        g_ad2[n] = acc0 * a2d[0] + acc1 * a2d[1];
    }
}

// ---------------- layer-2 aggregation: thread per dst node -> d_out ----------------
__global__ void agg2_kernel(const float* __restrict__ b2, float* __restrict__ out) {
    int n = blockIdx.x * blockDim.x + threadIdx.x;
    if (n >= N_NODESK) return;
    float adn = g_ad2[n];
    int beg = g_rowptr[n], end = g_rowptr[n + 1];
    float den = 0.f, o0 = 0.f, o1 = 0.f;
    for (int e = beg - 1; e < end; ++e) {
        int s = (e < beg) ? n : g_col[e];
        float w = expf(lrelu02(g_as2[s] + adn));
        den += w;
        o0 += w * g_h2[s * 2 + 0];
        o1 += w * g_h2[s * 2 + 1];
    }
    float r = 1.f / den;
    out[n * 2 + 0] = o0 * r + b2[0];
    out[n * 2 + 1] = o1 * r + b2[1];
}

// ---------------- launch ----------------
extern "C" void kernel_launch(void* const* d_in, const int* in_sizes, int n_in,
                              void* d_out, int out_size) {
    const float* x    = (const float*)d_in[0];
    const int*   ei   = (const int*)d_in[1];
    const float* W1   = (const float*)d_in[3];
    const float* a1s  = (const float*)d_in[4];
    const float* a1d  = (const float*)d_in[5];
    const float* b1   = (const float*)d_in[6];
    const float* W2   = (const float*)d_in[7];
    const float* a2s  = (const float*)d_in[8];
    const float* a2d  = (const float*)d_in[9];
    const float* b2   = (const float*)d_in[10];
    float* out = (float*)d_out;

    const int* src = ei;
    const int* dst = ei + N_EDGESK;

    // CSR build
    zero_cnt_kernel<<<(N_NODESK + 255) / 256, 256>>>();
    hist_kernel<<<(N_EDGESK + 255) / 256, 256>>>(dst);
    blocksum_kernel<<<NBLK_SCAN, 256>>>();
    scantop_kernel<<<1, 256>>>();
    scanlocal_kernel<<<NBLK_SCAN, 256>>>();
    scatter_kernel<<<(N_EDGESK + 255) / 256, 256>>>(src, dst);

    // layer 1
    sgemm_kernel<<<dim3(C1K / 128, (N_NODESK + 127) / 128), 256>>>(x, W1);
    alpha1_kernel<<<(N_NODESK * HEADSK + 255) / 256, 256>>>(a1s, a1d);
    agg1_kernel<<<(N_NODESK * 32 + 255) / 256, 256>>>(b1, W2, a2s, a2d);

    // layer 2
    agg2_kernel<<<(N_NODESK + 255) / 256, 256>>>(b2, out);
}